// round 4
// baseline (speedup 1.0000x reference)
#include <cuda_runtime.h>
#include <math.h>

#define NN 4096
#define CC 256
#define NH 8
#define HD 32

// Scratch (allocation-free rule: __device__ globals)
__device__ float g_Q[NN * CC];
__device__ float g_K[NN * CC];
__device__ float g_V[NN * CC];
__device__ float g_Mb[NN * CC];
__device__ float g_Y[NN * CC];

// ---------------------------------------------------------------------------
// Fast exp2 on the FMA/ALU pipes (no MUFU). Valid for x <= 0 (softmax args).
// Round-to-nearest via magic constant; degree-5 poly on f in [-0.5, 0.5];
// integer part added straight into the exponent bits. Clamp at -120 so the
// exponent add cannot underflow-wrap.
// ---------------------------------------------------------------------------
__device__ __forceinline__ float fexp2(float x)
{
    x = fmaxf(x, -120.0f);
    const float MAGIC = 12582912.0f;               // 1.5 * 2^23
    float z = __fadd_rn(x, MAGIC);                 // low mantissa bits = round(x)
    float f = __fadd_rn(x, -__fadd_rn(z, -MAGIC)); // f in [-0.5, 0.5]
    int   i = __float_as_int(z) << 23;             // n << 23 (rest wraps away)
    float p = 1.0f + f * (0.69314718f +
              f * (0.24022651f +
              f * (0.05550411f +
              f * (0.00961813f +
              f *  0.00133336f))));
    return __int_as_float(__float_as_int(p) + i);
}

// ---------------------------------------------------------------------------
// GEMM: Out[4096,256] = A[4096,256] @ B[256,256] + bias (+ optional residual)
// Tiles: BM=64, BN=64, BK=16; 256 threads, 4x4 microtile per thread.
// ---------------------------------------------------------------------------
__global__ __launch_bounds__(256) void gemm_kernel(
    const float* __restrict__ A, const float* __restrict__ B,
    const float* __restrict__ bias, const float* __restrict__ res,
    float* __restrict__ Out)
{
    __shared__ __align__(16) float As[16][68];  // [k][m], padded
    __shared__ __align__(16) float Bs[16][68];  // [k][n], padded

    const int t  = threadIdx.x;
    const int tx = t & 15;        // n microtile
    const int ty = t >> 4;        // m microtile
    const int n0 = blockIdx.x * 64;
    const int m0 = blockIdx.y * 64;

    float acc[4][4] = {};

    for (int k0 = 0; k0 < CC; k0 += 16) {
        {
            const int arow = t >> 2;      // 0..63
            const int af4  = t & 3;       // 0..3
            float4 a = *(const float4*)&A[(m0 + arow) * CC + k0 + af4 * 4];
            As[af4 * 4 + 0][arow] = a.x;
            As[af4 * 4 + 1][arow] = a.y;
            As[af4 * 4 + 2][arow] = a.z;
            As[af4 * 4 + 3][arow] = a.w;
            const int brow = t >> 4;      // 0..15
            const int bf4  = t & 15;      // 0..15
            *(float4*)&Bs[brow][bf4 * 4] =
                *(const float4*)&B[(k0 + brow) * CC + n0 + bf4 * 4];
        }
        __syncthreads();

        #pragma unroll
        for (int k = 0; k < 16; k++) {
            float4 a4 = *(float4*)&As[k][ty * 4];
            float4 b4 = *(float4*)&Bs[k][tx * 4];
            float av[4] = {a4.x, a4.y, a4.z, a4.w};
            float bv[4] = {b4.x, b4.y, b4.z, b4.w};
            #pragma unroll
            for (int i = 0; i < 4; i++)
                #pragma unroll
                for (int j = 0; j < 4; j++)
                    acc[i][j] += av[i] * bv[j];
        }
        __syncthreads();
    }

    #pragma unroll
    for (int i = 0; i < 4; i++) {
        const int row = m0 + ty * 4 + i;
        const int col = n0 + tx * 4;
        float4 bb = *(const float4*)&bias[col];
        float4 v;
        v.x = acc[i][0] + bb.x;
        v.y = acc[i][1] + bb.y;
        v.z = acc[i][2] + bb.z;
        v.w = acc[i][3] + bb.w;
        if (res) {
            float4 r = *(const float4*)&res[row * CC + col];
            v.x += r.x; v.y += r.y; v.z += r.z; v.w += r.w;
        }
        *(float4*)&Out[row * CC + col] = v;
    }
}

// ---------------------------------------------------------------------------
// Flash attention: grid (NN/64, NH), 64 threads per block,
// one thread = one query row. Online softmax (base-2 domain: scale*log2(e)
// folded into q) over all 4096 keys in 32-key SMEM tiles. All exps run on
// the FMA pipe via fexp2 — no MUFU bottleneck.
// ---------------------------------------------------------------------------
__global__ __launch_bounds__(64) void attn_kernel(
    const float* __restrict__ scale_p)
{
    __shared__ __align__(16) float Ks[32][32];
    __shared__ __align__(16) float Vs[32][32];

    const int h  = blockIdx.y;
    const int qi = blockIdx.x * 64 + threadIdx.x;
    const float qmul = (*scale_p) * 1.4426950408889634f;  // scale * log2(e)

    float q[32];
    {
        const float* qr = g_Q + qi * CC + h * HD;
        #pragma unroll
        for (int d = 0; d < 32; d++) q[d] = qr[d] * qmul;
    }
    float o[32] = {};
    float m = -1e30f;   // running max in log2 domain
    float l = 0.f;

    for (int j0 = 0; j0 < NN; j0 += 32) {
        __syncthreads();
        {
            const int t = threadIdx.x;
            #pragma unroll
            for (int r = 0; r < 4; r++) {
                const int idx = t + r * 64;   // 0..255
                const int row = idx >> 3;     // 0..31
                const int f4  = idx & 7;      // 0..7
                *(float4*)&Ks[row][f4 * 4] =
                    *(const float4*)&g_K[(j0 + row) * CC + h * HD + f4 * 4];
                *(float4*)&Vs[row][f4 * 4] =
                    *(const float4*)&g_V[(j0 + row) * CC + h * HD + f4 * 4];
            }
        }
        __syncthreads();

        // S = q . K^T for 32 keys (in log2 domain)
        float s[32];
        #pragma unroll
        for (int j = 0; j < 32; j++) s[j] = 0.f;
        #pragma unroll
        for (int d4 = 0; d4 < 8; d4++) {
            #pragma unroll
            for (int j = 0; j < 32; j++) {
                float4 kv = *(float4*)&Ks[j][d4 * 4];
                s[j] += q[d4 * 4 + 0] * kv.x + q[d4 * 4 + 1] * kv.y
                      + q[d4 * 4 + 2] * kv.z + q[d4 * 4 + 3] * kv.w;
            }
        }

        // Online softmax update (base 2)
        float mn = m;
        #pragma unroll
        for (int j = 0; j < 32; j++) mn = fmaxf(mn, s[j]);
        const float corr = fexp2(m - mn);
        m = mn;
        l *= corr;
        #pragma unroll
        for (int d = 0; d < 32; d++) o[d] *= corr;

        #pragma unroll
        for (int j = 0; j < 32; j++) {
            const float p = fexp2(s[j] - m);
            l += p;
            #pragma unroll
            for (int d4 = 0; d4 < 8; d4++) {
                float4 vv = *(float4*)&Vs[j][d4 * 4];
                o[d4 * 4 + 0] += p * vv.x;
                o[d4 * 4 + 1] += p * vv.y;
                o[d4 * 4 + 2] += p * vv.z;
                o[d4 * 4 + 3] += p * vv.w;
            }
        }
    }

    const float inv = 1.f / l;
    float* orow = g_Mb + qi * CC + h * HD;
    #pragma unroll
    for (int d4 = 0; d4 < 8; d4++) {
        float4 v;
        v.x = o[d4 * 4 + 0] * inv;
        v.y = o[d4 * 4 + 1] * inv;
        v.z = o[d4 * 4 + 2] * inv;
        v.w = o[d4 * 4 + 3] * inv;
        *(float4*)&orow[d4 * 4] = v;
    }
}

// ---------------------------------------------------------------------------
// LayerNorm: one warp per row (256 cols -> 8 per lane). grid 512, block (32,8)
// ---------------------------------------------------------------------------
__global__ __launch_bounds__(256) void ln_kernel(
    const float* __restrict__ gamma, const float* __restrict__ beta,
    float* __restrict__ out)
{
    const int row  = blockIdx.x * 8 + threadIdx.y;
    const int lane = threadIdx.x;
    const float* y = g_Y + row * CC;

    float v[8];
    float sum = 0.f;
    #pragma unroll
    for (int i = 0; i < 8; i++) {
        v[i] = y[lane + i * 32];
        sum += v[i];
    }
    #pragma unroll
    for (int off = 16; off; off >>= 1)
        sum += __shfl_xor_sync(0xffffffffu, sum, off);
    const float mu = sum * (1.f / 256.f);

    float var = 0.f;
    #pragma unroll
    for (int i = 0; i < 8; i++) {
        const float d = v[i] - mu;
        var += d * d;
    }
    #pragma unroll
    for (int off = 16; off; off >>= 1)
        var += __shfl_xor_sync(0xffffffffu, var, off);
    const float rstd = rsqrtf(var * (1.f / 256.f) + 1e-5f);

    #pragma unroll
    for (int i = 0; i < 8; i++) {
        const int c = lane + i * 32;
        out[row * CC + c] = (v[i] - mu) * rstd * gamma[c] + beta[c];
    }
}

// ---------------------------------------------------------------------------
extern "C" void kernel_launch(void* const* d_in, const int* in_sizes, int n_in,
                              void* d_out, int out_size)
{
    const float* x     = (const float*)d_in[0];
    const float* Wq    = (const float*)d_in[1];
    const float* bq    = (const float*)d_in[2];
    const float* Wk    = (const float*)d_in[3];
    const float* bk    = (const float*)d_in[4];
    const float* Wv    = (const float*)d_in[5];
    const float* bv    = (const float*)d_in[6];
    const float* scale = (const float*)d_in[7];
    const float* Wo    = (const float*)d_in[8];
    const float* bo    = (const float*)d_in[9];
    const float* gamma = (const float*)d_in[10];
    const float* beta  = (const float*)d_in[11];
    float* out = (float*)d_out;

    float *Qp, *Kp, *Vp, *Mp, *Yp;
    cudaGetSymbolAddress((void**)&Qp, g_Q);
    cudaGetSymbolAddress((void**)&Kp, g_K);
    cudaGetSymbolAddress((void**)&Vp, g_V);
    cudaGetSymbolAddress((void**)&Mp, g_Mb);
    cudaGetSymbolAddress((void**)&Yp, g_Y);

    const dim3 gg(CC / 64, NN / 64);   // (4, 64)
    gemm_kernel<<<gg, 256>>>(x, Wq, bq, nullptr, Qp);
    gemm_kernel<<<gg, 256>>>(x, Wk, bk, nullptr, Kp);
    gemm_kernel<<<gg, 256>>>(x, Wv, bv, nullptr, Vp);

    attn_kernel<<<dim3(NN / 64, NH), 64>>>(scale);

    gemm_kernel<<<gg, 256>>>(Mp, Wo, bo, x, Yp);

    ln_kernel<<<512, dim3(32, 8)>>>(gamma, beta, out);
}

// round 6
// speedup vs baseline: 1.2561x; 1.2561x over previous
#include <cuda_runtime.h>
#include <math.h>

#define NN 4096
#define CC 256
#define NH 8
#define HD 32
#define NSPLIT 2
#define KS_PER (NN / NSPLIT)

typedef unsigned long long u64;

// Scratch (allocation-free rule: __device__ globals)
__device__ float g_Q[NN * CC];
__device__ float g_K[NN * CC];
__device__ float g_V[NN * CC];
__device__ float g_Mb[NN * CC];
__device__ float g_Y[NN * CC];
__device__ float g_Po[NSPLIT][NN * CC];   // unnormalized partial outputs
__device__ float g_Pm[NSPLIT][NN * NH];   // partial running max (log2 domain)
__device__ float g_Pl[NSPLIT][NN * NH];   // partial denominators

// ---------------------------------------------------------------------------
// Packed f32x2 helpers (FFMA2 path — ptxas only emits these from PTX)
// ---------------------------------------------------------------------------
__device__ __forceinline__ u64 ffma2(u64 a, u64 b, u64 c) {
    u64 d; asm("fma.rn.f32x2 %0, %1, %2, %3;" : "=l"(d) : "l"(a), "l"(b), "l"(c));
    return d;
}
__device__ __forceinline__ u64 fadd2(u64 a, u64 b) {
    u64 d; asm("add.rn.f32x2 %0, %1, %2;" : "=l"(d) : "l"(a), "l"(b));
    return d;
}
__device__ __forceinline__ u64 fmul2(u64 a, u64 b) {
    u64 d; asm("mul.rn.f32x2 %0, %1, %2;" : "=l"(d) : "l"(a), "l"(b));
    return d;
}
__device__ __forceinline__ u64 pack2(float lo, float hi) {
    u64 d; asm("mov.b64 %0, {%1, %2};" : "=l"(d) : "f"(lo), "f"(hi));
    return d;
}
__device__ __forceinline__ void unpack2(u64 v, float& lo, float& hi) {
    asm("mov.b64 {%0, %1}, %2;" : "=f"(lo), "=f"(hi) : "l"(v));
}

// ---------------------------------------------------------------------------
// Scalar fast exp2 on FMA/ALU pipes (x <= 0). Used for rare per-tile corr and
// in the combine kernel.
// ---------------------------------------------------------------------------
__device__ __forceinline__ float fexp2(float x)
{
    x = fmaxf(x, -120.0f);
    const float MAGIC = 12582912.0f;               // 1.5 * 2^23
    float z = __fadd_rn(x, MAGIC);
    float f = __fadd_rn(x, -__fadd_rn(z, -MAGIC));
    int   i = __float_as_int(z) << 23;
    float p = 1.0f + f * (0.69314718f +
              f * (0.24022651f +
              f * (0.05550411f +
              f * (0.00961813f +
              f *  0.00133336f))));
    return __int_as_float(__float_as_int(p) + i);
}

// Pairwise exp2 for two values (both <= 0): poly on FMA pipe (packed),
// exponent-bit integer adds on ALU pipe.
__device__ __forceinline__ u64 fexp2x2(float a, float b)
{
    a = fmaxf(a, -120.0f);
    b = fmaxf(b, -120.0f);
    const u64 MAGIC2 = pack2(12582912.0f, 12582912.0f);
    const u64 NMAGIC2 = pack2(-12582912.0f, -12582912.0f);
    const u64 NONE2  = pack2(-1.0f, -1.0f);
    const u64 C5 = pack2(0.00133336f, 0.00133336f);
    const u64 C4 = pack2(0.00961813f, 0.00961813f);
    const u64 C3 = pack2(0.05550411f, 0.05550411f);
    const u64 C2 = pack2(0.24022651f, 0.24022651f);
    const u64 C1 = pack2(0.69314718f, 0.69314718f);
    const u64 ONE2 = pack2(1.0f, 1.0f);

    u64 x2 = pack2(a, b);
    u64 z2 = fadd2(x2, MAGIC2);             // low mantissa bits hold round(x)
    u64 t2 = fadd2(z2, NMAGIC2);            // t = round(x)
    u64 f2 = ffma2(t2, NONE2, x2);          // f = x - round(x), in [-0.5, 0.5]
    u64 p2 = ffma2(f2, C5, C4);
    p2 = ffma2(f2, p2, C3);
    p2 = ffma2(f2, p2, C2);
    p2 = ffma2(f2, p2, C1);
    p2 = ffma2(f2, p2, ONE2);
    unsigned int zlo = (unsigned int)z2, zhi = (unsigned int)(z2 >> 32);
    unsigned int plo = (unsigned int)p2, phi = (unsigned int)(p2 >> 32);
    plo += zlo << 23;                       // ALU-pipe exponent add
    phi += zhi << 23;
    return ((u64)phi << 32) | plo;
}

// ---------------------------------------------------------------------------
// GEMM: Out[4096,256] = A[4096,256] @ B[256,256] + bias (+ optional residual)
// ---------------------------------------------------------------------------
__global__ __launch_bounds__(256) void gemm_kernel(
    const float* __restrict__ A, const float* __restrict__ B,
    const float* __restrict__ bias, const float* __restrict__ res,
    float* __restrict__ Out)
{
    __shared__ __align__(16) float As[16][68];
    __shared__ __align__(16) float Bs[16][68];

    const int t  = threadIdx.x;
    const int tx = t & 15;
    const int ty = t >> 4;
    const int n0 = blockIdx.x * 64;
    const int m0 = blockIdx.y * 64;

    float acc[4][4] = {};

    for (int k0 = 0; k0 < CC; k0 += 16) {
        {
            const int arow = t >> 2;
            const int af4  = t & 3;
            float4 a = *(const float4*)&A[(m0 + arow) * CC + k0 + af4 * 4];
            As[af4 * 4 + 0][arow] = a.x;
            As[af4 * 4 + 1][arow] = a.y;
            As[af4 * 4 + 2][arow] = a.z;
            As[af4 * 4 + 3][arow] = a.w;
            const int brow = t >> 4;
            const int bf4  = t & 15;
            *(float4*)&Bs[brow][bf4 * 4] =
                *(const float4*)&B[(k0 + brow) * CC + n0 + bf4 * 4];
        }
        __syncthreads();

        #pragma unroll
        for (int k = 0; k < 16; k++) {
            float4 a4 = *(float4*)&As[k][ty * 4];
            float4 b4 = *(float4*)&Bs[k][tx * 4];
            float av[4] = {a4.x, a4.y, a4.z, a4.w};
            float bv[4] = {b4.x, b4.y, b4.z, b4.w};
            #pragma unroll
            for (int i = 0; i < 4; i++)
                #pragma unroll
                for (int j = 0; j < 4; j++)
                    acc[i][j] += av[i] * bv[j];
        }
        __syncthreads();
    }

    #pragma unroll
    for (int i = 0; i < 4; i++) {
        const int row = m0 + ty * 4 + i;
        const int col = n0 + tx * 4;
        float4 bb = *(const float4*)&bias[col];
        float4 v;
        v.x = acc[i][0] + bb.x;
        v.y = acc[i][1] + bb.y;
        v.z = acc[i][2] + bb.z;
        v.w = acc[i][3] + bb.w;
        if (res) {
            float4 r = *(const float4*)&res[row * CC + col];
            v.x += r.x; v.y += r.y; v.z += r.z; v.w += r.w;
        }
        *(float4*)&Out[row * CC + col] = v;
    }
}

// ---------------------------------------------------------------------------
// Flash attention, split-keys, packed f32x2 math.
// grid (NN/128, NH, NSPLIT), 128 threads; one thread = one query row.
// Each block covers keys [split*2048, split*2048+2048) for one head and
// writes unnormalized (o, m, l) partials.
// ---------------------------------------------------------------------------
__global__ __launch_bounds__(128, 3) void attn_kernel(
    const float* __restrict__ scale_p)
{
    __shared__ __align__(16) float Ks[32][32];
    __shared__ __align__(16) float Vs[32][32];

    const int h  = blockIdx.y;
    const int sp = blockIdx.z;
    const int qi = blockIdx.x * 128 + threadIdx.x;
    const float qmul = (*scale_p) * 1.4426950408889634f;  // scale * log2(e)

    // q packed: 16 f32x2
    u64 q2[16];
    {
        const float* qr = g_Q + qi * CC + h * HD;
        const u64 qmul2 = pack2(qmul, qmul);
        #pragma unroll
        for (int i = 0; i < 8; i++) {
            ulonglong2 r = *(const ulonglong2*)&qr[i * 4];
            q2[2 * i + 0] = fmul2(r.x, qmul2);
            q2[2 * i + 1] = fmul2(r.y, qmul2);
        }
    }

    u64 o2[16];
    #pragma unroll
    for (int i = 0; i < 16; i++) o2[i] = 0ull;
    u64 l2 = 0ull;
    float m = -1e30f;

    const int j_begin = sp * KS_PER;
    for (int j0 = j_begin; j0 < j_begin + KS_PER; j0 += 32) {
        __syncthreads();
        {
            const int t = threadIdx.x;
            #pragma unroll
            for (int r = 0; r < 2; r++) {
                const int idx = t + r * 128;   // 0..255
                const int row = idx >> 3;      // 0..31
                const int f4  = idx & 7;       // 0..7
                *(float4*)&Ks[row][f4 * 4] =
                    *(const float4*)&g_K[(j0 + row) * CC + h * HD + f4 * 4];
                *(float4*)&Vs[row][f4 * 4] =
                    *(const float4*)&g_V[(j0 + row) * CC + h * HD + f4 * 4];
            }
        }
        __syncthreads();

        // S = q . K^T for 32 keys (log2 domain), packed along d
        float s[32];
        #pragma unroll
        for (int j = 0; j < 32; j++) {
            u64 acc = 0ull;
            #pragma unroll
            for (int d4 = 0; d4 < 8; d4++) {
                ulonglong2 kk = *(const ulonglong2*)&Ks[j][d4 * 4];
                acc = ffma2(q2[2 * d4 + 0], kk.x, acc);
                acc = ffma2(q2[2 * d4 + 1], kk.y, acc);
            }
            float lo, hi;
            unpack2(acc, lo, hi);
            s[j] = lo + hi;
        }

        // Online softmax update (base 2)
        float mn = m;
        #pragma unroll
        for (int j = 0; j < 32; j++) mn = fmaxf(mn, s[j]);
        const float corr = fexp2(m - mn);
        m = mn;
        const u64 corr2 = pack2(corr, corr);
        l2 = fmul2(l2, corr2);
        #pragma unroll
        for (int i = 0; i < 16; i++) o2[i] = fmul2(o2[i], corr2);

        #pragma unroll
        for (int jp = 0; jp < 16; jp++) {
            const u64 p2 = fexp2x2(s[2 * jp] - m, s[2 * jp + 1] - m);
            l2 = fadd2(l2, p2);
            float pa, pb;
            unpack2(p2, pa, pb);
            const u64 pa2 = pack2(pa, pa);
            const u64 pb2 = pack2(pb, pb);
            #pragma unroll
            for (int d4 = 0; d4 < 8; d4++) {
                ulonglong2 va = *(const ulonglong2*)&Vs[2 * jp][d4 * 4];
                o2[2 * d4 + 0] = ffma2(pa2, va.x, o2[2 * d4 + 0]);
                o2[2 * d4 + 1] = ffma2(pa2, va.y, o2[2 * d4 + 1]);
            }
            #pragma unroll
            for (int d4 = 0; d4 < 8; d4++) {
                ulonglong2 vb = *(const ulonglong2*)&Vs[2 * jp + 1][d4 * 4];
                o2[2 * d4 + 0] = ffma2(pb2, vb.x, o2[2 * d4 + 0]);
                o2[2 * d4 + 1] = ffma2(pb2, vb.y, o2[2 * d4 + 1]);
            }
        }
    }

    // Write partials (unnormalized)
    float llo, lhi;
    unpack2(l2, llo, lhi);
    g_Pm[sp][qi * NH + h] = m;
    g_Pl[sp][qi * NH + h] = llo + lhi;
    float* orow = &g_Po[sp][qi * CC + h * HD];
    #pragma unroll
    for (int i = 0; i < 8; i++) {
        ulonglong2 v;
        v.x = o2[2 * i + 0];
        v.y = o2[2 * i + 1];
        *(ulonglong2*)&orow[i * 4] = v;
    }
}

// ---------------------------------------------------------------------------
// Combine the NSPLIT partials: flash-merge. One thread per (q, h).
// ---------------------------------------------------------------------------
__global__ __launch_bounds__(256) void attn_combine_kernel()
{
    const int idx = blockIdx.x * 256 + threadIdx.x;   // 0 .. NN*NH-1
    const int qi = idx >> 3;
    const int h  = idx & 7;

    const float m0 = g_Pm[0][idx], m1 = g_Pm[1][idx];
    const float l0 = g_Pl[0][idx], l1 = g_Pl[1][idx];
    const float M  = fmaxf(m0, m1);
    const float w0 = fexp2(m0 - M);
    const float w1 = fexp2(m1 - M);
    const float inv = 1.0f / (l0 * w0 + l1 * w1);
    const float a0 = w0 * inv, a1 = w1 * inv;

    const float* p0 = &g_Po[0][qi * CC + h * HD];
    const float* p1 = &g_Po[1][qi * CC + h * HD];
    float* out = &g_Mb[qi * CC + h * HD];
    #pragma unroll
    for (int i = 0; i < 8; i++) {
        float4 x0 = *(const float4*)&p0[i * 4];
        float4 x1 = *(const float4*)&p1[i * 4];
        float4 v;
        v.x = x0.x * a0 + x1.x * a1;
        v.y = x0.y * a0 + x1.y * a1;
        v.z = x0.z * a0 + x1.z * a1;
        v.w = x0.w * a0 + x1.w * a1;
        *(float4*)&out[i * 4] = v;
    }
}

// ---------------------------------------------------------------------------
// LayerNorm: one warp per row. grid 512, block (32,8)
// ---------------------------------------------------------------------------
__global__ __launch_bounds__(256) void ln_kernel(
    const float* __restrict__ gamma, const float* __restrict__ beta,
    float* __restrict__ out)
{
    const int row  = blockIdx.x * 8 + threadIdx.y;
    const int lane = threadIdx.x;
    const float* y = g_Y + row * CC;

    float v[8];
    float sum = 0.f;
    #pragma unroll
    for (int i = 0; i < 8; i++) {
        v[i] = y[lane + i * 32];
        sum += v[i];
    }
    #pragma unroll
    for (int off = 16; off; off >>= 1)
        sum += __shfl_xor_sync(0xffffffffu, sum, off);
    const float mu = sum * (1.f / 256.f);

    float var = 0.f;
    #pragma unroll
    for (int i = 0; i < 8; i++) {
        const float d = v[i] - mu;
        var += d * d;
    }
    #pragma unroll
    for (int off = 16; off; off >>= 1)
        var += __shfl_xor_sync(0xffffffffu, var, off);
    const float rstd = rsqrtf(var * (1.f / 256.f) + 1e-5f);

    #pragma unroll
    for (int i = 0; i < 8; i++) {
        const int c = lane + i * 32;
        out[row * CC + c] = (v[i] - mu) * rstd * gamma[c] + beta[c];
    }
}

// ---------------------------------------------------------------------------
extern "C" void kernel_launch(void* const* d_in, const int* in_sizes, int n_in,
                              void* d_out, int out_size)
{
    const float* x     = (const float*)d_in[0];
    const float* Wq    = (const float*)d_in[1];
    const float* bq    = (const float*)d_in[2];
    const float* Wk    = (const float*)d_in[3];
    const float* bk    = (const float*)d_in[4];
    const float* Wv    = (const float*)d_in[5];
    const float* bv    = (const float*)d_in[6];
    const float* scale = (const float*)d_in[7];
    const float* Wo    = (const float*)d_in[8];
    const float* bo    = (const float*)d_in[9];
    const float* gamma = (const float*)d_in[10];
    const float* beta  = (const float*)d_in[11];
    float* out = (float*)d_out;

    float *Qp, *Kp, *Vp, *Mp, *Yp;
    cudaGetSymbolAddress((void**)&Qp, g_Q);
    cudaGetSymbolAddress((void**)&Kp, g_K);
    cudaGetSymbolAddress((void**)&Vp, g_V);
    cudaGetSymbolAddress((void**)&Mp, g_Mb);
    cudaGetSymbolAddress((void**)&Yp, g_Y);

    const dim3 gg(CC / 64, NN / 64);   // (4, 64)
    gemm_kernel<<<gg, 256>>>(x, Wq, bq, nullptr, Qp);
    gemm_kernel<<<gg, 256>>>(x, Wk, bk, nullptr, Kp);
    gemm_kernel<<<gg, 256>>>(x, Wv, bv, nullptr, Vp);

    attn_kernel<<<dim3(NN / 128, NH, NSPLIT), 128>>>(scale);
    attn_combine_kernel<<<(NN * NH) / 256, 256>>>();

    gemm_kernel<<<gg, 256>>>(Mp, Wo, bo, x, Yp);

    ln_kernel<<<512, dim3(32, 8)>>>(gamma, beta, out);
}